// round 14
// baseline (speedup 1.0000x reference)
#include <cuda_runtime.h>
#include <cstdint>

#define T_DIM 2048
#define NI    4096
#define L     32
#define F     16
#define TC    128             // t per CTA
#define CHB   16              // channels per CTA
#define RWS   190             // staged rows: t0-63 .. t0+126
#define XS    20              // smem row stride in floats (=4 mod 16 -> conflict-free LDS)
#define NSTEP (TC / 8)        // 16 chain steps

__device__ float g_wh[L * F];  // [k][f], lag-reversed+normalized, tf32-rounded

__device__ __forceinline__ float tf32r(float x) {
    uint32_t u;
    asm("cvt.rna.tf32.f32 %0, %1;" : "=r"(u) : "f"(x));
    return __uint_as_float(u);
}

#define MMA(c0,c1,c2,c3,a0,a1,a2,a3,b0,b1)                              \
    asm("mma.sync.aligned.m16n8k8.row.col.f32.tf32.tf32.f32 "           \
        "{%0,%1,%2,%3}, {%4,%5,%6,%7}, {%8,%9}, {%0,%1,%2,%3};"         \
        : "+f"(c0), "+f"(c1), "+f"(c2), "+f"(c3)                        \
        : "r"(a0), "r"(a1), "r"(a2), "r"(a3), "r"(b0), "r"(b1))

// pos-constraint + l2-normalize + lag-reverse + tf32 round
__global__ void prep_kernel(const float* __restrict__ w) {
    int f = threadIdx.x;
    if (f < F) {
        float col[L];
        float s = 0.f;
#pragma unroll
        for (int j = 0; j < L; j++) {
            float v = fmaxf(w[j * F + f], 0.f);
            col[j] = v;
            s += v * v;
        }
        float inv = rsqrtf(fmaxf(s, 1e-12f));
#pragma unroll
        for (int k = 0; k < L; k++)
            g_wh[k * F + f] = tf32r(col[L - 1 - k] * inv);  // W[k][f] = w_pn[31-k][f]
    }
}

// CTA: 16 channels x 128 t, 256 threads (8 warps). M-dim = channels: one
// mma-pair = 16ch x 16f at ONE t -> warp STG.128s are fully contiguous lines.
// Warp w runs one chain t = t0 + w + 8n, stepping t by 8: A_{t+8}[k]=A_t[k+4]
// rolls 14/16 A-regs (compile-time renames), 2 fresh LDS per step.
__global__ __launch_bounds__(256, 4) void conv_kernel(const float* __restrict__ x,
                                                      const float* __restrict__ bias,
                                                      float* __restrict__ out) {
    __shared__ float sx[RWS * XS];     // [row][16ch + pad], row = tau-(t0-63)

    const int tid  = threadIdx.x;
    const int w    = tid >> 5;
    const int lane = tid & 31;
    const int g    = lane >> 2;       // groupID (channel row)
    const int tg   = lane & 3;        // threadID_in_group
    const int ib   = blockIdx.x * CHB;
    const int t0   = blockIdx.y * TC;

    // ---- stage x window: sx[row][ch], tf32-rounded, zero-fill tau<0 ----
    if (t0 >= 63) {
#pragma unroll
        for (int p = 0; p < 3; p++) {
            int idx = tid + p * 256;            // 760 float4 items = 190 rows x 4
            if (idx < RWS * 4) {
                int row = idx >> 2;
                int q   = idx & 3;
                float4 v = *reinterpret_cast<const float4*>(
                    x + (long)(t0 - 63 + row) * NI + ib + 4 * q);
                float4 r;
                r.x = tf32r(v.x); r.y = tf32r(v.y); r.z = tf32r(v.z); r.w = tf32r(v.w);
                *reinterpret_cast<float4*>(sx + row * XS + 4 * q) = r;
            }
        }
    } else {
#pragma unroll
        for (int p = 0; p < 3; p++) {
            int idx = tid + p * 256;
            if (idx < RWS * 4) {
                int row = idx >> 2;
                int q   = idx & 3;
                int tau = t0 - 63 + row;
                float4 r = make_float4(0.f, 0.f, 0.f, 0.f);
                if (tau >= 0) {
                    float4 v = *reinterpret_cast<const float4*>(
                        x + (long)tau * NI + ib + 4 * q);
                    r.x = tf32r(v.x); r.y = tf32r(v.y); r.z = tf32r(v.z); r.w = tf32r(v.w);
                }
                *reinterpret_cast<float4*>(sx + row * XS + 4 * q) = r;
            }
        }
    }

    // ---- B fragments with permuted filter columns ----
    // ntile0 col c -> f = (c even) ? 2c : 2c-1 ; ntile1 col c -> (c even) ? 2c+2 : 2c+1
    const int fc0 = (g & 1) ? (2 * g - 1) : (2 * g);
    const int fc1 = (g & 1) ? (2 * g + 1) : (2 * g + 2);
    uint32_t bh[4][2][2];
#pragma unroll
    for (int s = 0; s < 4; s++) {
        int k0 = s * 8 + tg;
        bh[s][0][0] = __float_as_uint(g_wh[k0 * F + fc0]);
        bh[s][0][1] = __float_as_uint(g_wh[(k0 + 4) * F + fc0]);
        bh[s][1][0] = __float_as_uint(g_wh[k0 * F + fc1]);
        bh[s][1][1] = __float_as_uint(g_wh[(k0 + 4) * F + fc1]);
    }

    const float4 bq = reinterpret_cast<const float4*>(bias)[tg];

    __syncthreads();

    // lane's smem base: row (w + 2tg), channel g
    const float* pA = sx + (w + 2 * tg) * XS + g;

    // A-regs: A0[s]=A[g][8s+tg], A1[s]=A[g+8][8s+tg], A2[s]=A[g][8s+tg+4], A3=A[g+8][..]
    float A0[4], A1[4], A2[4], A3[4];
#pragma unroll
    for (int s = 0; s < 4; s++) {
        A0[s] = pA[(16 * s) * XS];
        A1[s] = pA[(16 * s) * XS + 8];
        A2[s] = pA[(16 * s + 8) * XS];
        A3[s] = pA[(16 * s + 8) * XS + 8];
    }

    float* po = out + (long)(t0 + w) * (NI * F) + ib * F + 16 * g + 4 * tg;
    const long tstride = (long)8 * (NI * F);

#pragma unroll
    for (int n = 0; n < NSTEP; n++) {
        float h00 = bq.x, h01 = bq.y, h02 = bq.x, h03 = bq.y;
        float h10 = bq.z, h11 = bq.w, h12 = bq.z, h13 = bq.w;

#pragma unroll
        for (int s = 0; s < 4; s++) {
            uint32_t a0 = __float_as_uint(A0[s]);
            uint32_t a1 = __float_as_uint(A1[s]);
            uint32_t a2 = __float_as_uint(A2[s]);
            uint32_t a3 = __float_as_uint(A3[s]);
            MMA(h00, h01, h02, h03, a0, a1, a2, a3, bh[s][0][0], bh[s][0][1]);
            MMA(h10, h11, h12, h13, a0, a1, a2, a3, bh[s][1][0], bh[s][1][1]);
        }

        // stores: ch g (contiguous 512B across warp) and ch g+8; streaming hint
        float4 va;
        va.x = fmaxf(h00, 0.f);
        va.y = fmaxf(h01, 0.f);
        va.z = fmaxf(h10, 0.f);
        va.w = fmaxf(h11, 0.f);
        __stcs(reinterpret_cast<float4*>(po), va);
        float4 vb;
        vb.x = fmaxf(h02, 0.f);
        vb.y = fmaxf(h03, 0.f);
        vb.z = fmaxf(h12, 0.f);
        vb.w = fmaxf(h13, 0.f);
        __stcs(reinterpret_cast<float4*>(po + 128), vb);  // +8 channels * 16 floats
        po += tstride;

        // roll A window: t -> t+8  (A_{t+8}[k] = A_t[k+4]); renames, not MOVs
        if (n < NSTEP - 1) {
            float f0 = pA[(8 * n + 64) * XS];
            float f1 = pA[(8 * n + 64) * XS + 8];
#pragma unroll
            for (int s = 0; s < 4; s++) {
                A0[s] = A2[s];
                A1[s] = A3[s];
                if (s < 3) { A2[s] = A0[s + 1]; A3[s] = A1[s + 1]; }
            }
            A2[3] = f0;
            A3[3] = f1;
        }
    }
}

extern "C" void kernel_launch(void* const* d_in, const int* in_sizes, int n_in,
                              void* d_out, int out_size) {
    const float* x    = (const float*)d_in[0];
    const float* w    = (const float*)d_in[1];
    const float* bias = (const float*)d_in[2];
    float* out        = (float*)d_out;

    prep_kernel<<<1, 32>>>(w);

    dim3 grid(NI / CHB, T_DIM / TC);
    conv_kernel<<<grid, 256>>>(x, bias, out);
}

// round 15
// speedup vs baseline: 1.0176x; 1.0176x over previous
#include <cuda_runtime.h>
#include <cstdint>

#define T_DIM 2048
#define NI    4096
#define L     32
#define F     16
#define TC    64              // t per CTA
#define CHB   16              // channels per CTA
#define RWS   126             // staged rows: t0-63 .. t0+62
#define XS    20              // smem row stride in floats (=4 mod 16 -> conflict-free LDS)
#define NSTEP (TC / 8)        // 8 chain steps

__device__ float g_wh[L * F];  // [k][f], lag-reversed+normalized, tf32-rounded

__device__ __forceinline__ float tf32r(float x) {
    uint32_t u;
    asm("cvt.rna.tf32.f32 %0, %1;" : "=r"(u) : "f"(x));
    return __uint_as_float(u);
}

#define MMA(c0,c1,c2,c3,a0,a1,a2,a3,b0,b1)                              \
    asm("mma.sync.aligned.m16n8k8.row.col.f32.tf32.tf32.f32 "           \
        "{%0,%1,%2,%3}, {%4,%5,%6,%7}, {%8,%9}, {%0,%1,%2,%3};"         \
        : "+f"(c0), "+f"(c1), "+f"(c2), "+f"(c3)                        \
        : "r"(a0), "r"(a1), "r"(a2), "r"(a3), "r"(b0), "r"(b1))

// pos-constraint + l2-normalize + lag-reverse + tf32 round
__global__ void prep_kernel(const float* __restrict__ w) {
    int f = threadIdx.x;
    if (f < F) {
        float col[L];
        float s = 0.f;
#pragma unroll
        for (int j = 0; j < L; j++) {
            float v = fmaxf(w[j * F + f], 0.f);
            col[j] = v;
            s += v * v;
        }
        float inv = rsqrtf(fmaxf(s, 1e-12f));
#pragma unroll
        for (int k = 0; k < L; k++)
            g_wh[k * F + f] = tf32r(col[L - 1 - k] * inv);  // W[k][f] = w_pn[31-k][f]
    }
}

// CTA: 16 channels x 64 t, 128 threads. M-dim = channels: one mma-pair =
// 16ch x 16f at ONE t -> warp STG.128s are fully contiguous lines.
// Warp w runs TWO INTERLEAVED chains (t = t0+2w+c+8n, c=0,1): 4 independent
// mma chains + 2 LDS streams per step to cover HMMA/LDS latency.
__global__ __launch_bounds__(128, 5) void conv_kernel(const float* __restrict__ x,
                                                      const float* __restrict__ bias,
                                                      float* __restrict__ out) {
    __shared__ float sx[RWS * XS];     // [row][16ch + pad], row = tau-(t0-63)

    const int tid  = threadIdx.x;
    const int w    = tid >> 5;
    const int lane = tid & 31;
    const int g    = lane >> 2;       // groupID (channel row)
    const int tg   = lane & 3;        // threadID_in_group
    const int ib   = blockIdx.x * CHB;
    const int t0   = blockIdx.y * TC;

    // ---- stage x window: sx[row][ch], tf32-rounded, zero-fill tau<0 ----
    if (t0 >= 63) {
#pragma unroll
        for (int p = 0; p < 4; p++) {
            int idx = tid + p * 128;            // 504 float4 items = 126 rows x 4
            if (idx < RWS * 4) {
                int row = idx >> 2;
                int q   = idx & 3;
                float4 v = *reinterpret_cast<const float4*>(
                    x + (long)(t0 - 63 + row) * NI + ib + 4 * q);
                float4 r;
                r.x = tf32r(v.x); r.y = tf32r(v.y); r.z = tf32r(v.z); r.w = tf32r(v.w);
                *reinterpret_cast<float4*>(sx + row * XS + 4 * q) = r;
            }
        }
    } else {
#pragma unroll
        for (int p = 0; p < 4; p++) {
            int idx = tid + p * 128;
            if (idx < RWS * 4) {
                int row = idx >> 2;
                int q   = idx & 3;
                int tau = t0 - 63 + row;
                float4 r = make_float4(0.f, 0.f, 0.f, 0.f);
                if (tau >= 0) {
                    float4 v = *reinterpret_cast<const float4*>(
                        x + (long)tau * NI + ib + 4 * q);
                    r.x = tf32r(v.x); r.y = tf32r(v.y); r.z = tf32r(v.z); r.w = tf32r(v.w);
                }
                *reinterpret_cast<float4*>(sx + row * XS + 4 * q) = r;
            }
        }
    }

    // ---- B fragments with permuted filter columns ----
    // ntile0 col c -> f = (c even) ? 2c : 2c-1 ; ntile1 col c -> (c even) ? 2c+2 : 2c+1
    const int fc0 = (g & 1) ? (2 * g - 1) : (2 * g);
    const int fc1 = (g & 1) ? (2 * g + 1) : (2 * g + 2);
    uint32_t bh[4][2][2];
#pragma unroll
    for (int s = 0; s < 4; s++) {
        int k0 = s * 8 + tg;
        bh[s][0][0] = __float_as_uint(g_wh[k0 * F + fc0]);
        bh[s][0][1] = __float_as_uint(g_wh[(k0 + 4) * F + fc0]);
        bh[s][1][0] = __float_as_uint(g_wh[k0 * F + fc1]);
        bh[s][1][1] = __float_as_uint(g_wh[(k0 + 4) * F + fc1]);
    }

    const float4 bq = reinterpret_cast<const float4*>(bias)[tg];

    __syncthreads();

    // two chains c=0,1: rt = 2w+c
    const float* pA0 = sx + (2 * w + 0 + 2 * tg) * XS + g;
    const float* pA1 = sx + (2 * w + 1 + 2 * tg) * XS + g;

    // A-regs per chain: A{0..3}[s]
    float A0a[4], A1a[4], A2a[4], A3a[4];   // chain 0
    float A0b[4], A1b[4], A2b[4], A3b[4];   // chain 1
#pragma unroll
    for (int s = 0; s < 4; s++) {
        A0a[s] = pA0[(16 * s) * XS];
        A1a[s] = pA0[(16 * s) * XS + 8];
        A2a[s] = pA0[(16 * s + 8) * XS];
        A3a[s] = pA0[(16 * s + 8) * XS + 8];
        A0b[s] = pA1[(16 * s) * XS];
        A1b[s] = pA1[(16 * s) * XS + 8];
        A2b[s] = pA1[(16 * s + 8) * XS];
        A3b[s] = pA1[(16 * s + 8) * XS + 8];
    }

    float* po0 = out + (long)(t0 + 2 * w) * (NI * F) + ib * F + 16 * g + 4 * tg;
    float* po1 = po0 + (long)(NI * F);
    const long tstride = (long)8 * (NI * F);

#pragma unroll
    for (int n = 0; n < NSTEP; n++) {
        // 4 independent accumulator chains (2 time-chains x 2 n-tiles)
        float p00 = bq.x, p01 = bq.y, p02 = bq.x, p03 = bq.y;
        float p10 = bq.z, p11 = bq.w, p12 = bq.z, p13 = bq.w;
        float q00 = bq.x, q01 = bq.y, q02 = bq.x, q03 = bq.y;
        float q10 = bq.z, q11 = bq.w, q12 = bq.z, q13 = bq.w;

#pragma unroll
        for (int s = 0; s < 4; s++) {
            uint32_t a0 = __float_as_uint(A0a[s]);
            uint32_t a1 = __float_as_uint(A1a[s]);
            uint32_t a2 = __float_as_uint(A2a[s]);
            uint32_t a3 = __float_as_uint(A3a[s]);
            uint32_t b0 = __float_as_uint(A0b[s]);
            uint32_t b1 = __float_as_uint(A1b[s]);
            uint32_t b2 = __float_as_uint(A2b[s]);
            uint32_t b3 = __float_as_uint(A3b[s]);
            MMA(p00, p01, p02, p03, a0, a1, a2, a3, bh[s][0][0], bh[s][0][1]);
            MMA(q00, q01, q02, q03, b0, b1, b2, b3, bh[s][0][0], bh[s][0][1]);
            MMA(p10, p11, p12, p13, a0, a1, a2, a3, bh[s][1][0], bh[s][1][1]);
            MMA(q10, q11, q12, q13, b0, b1, b2, b3, bh[s][1][0], bh[s][1][1]);
        }

        // stores (contiguous full lines across warp), streaming hint
        float4 v;
        v.x = fmaxf(p00, 0.f); v.y = fmaxf(p01, 0.f);
        v.z = fmaxf(p10, 0.f); v.w = fmaxf(p11, 0.f);
        __stcs(reinterpret_cast<float4*>(po0), v);
        v.x = fmaxf(p02, 0.f); v.y = fmaxf(p03, 0.f);
        v.z = fmaxf(p12, 0.f); v.w = fmaxf(p13, 0.f);
        __stcs(reinterpret_cast<float4*>(po0 + 128), v);
        v.x = fmaxf(q00, 0.f); v.y = fmaxf(q01, 0.f);
        v.z = fmaxf(q10, 0.f); v.w = fmaxf(q11, 0.f);
        __stcs(reinterpret_cast<float4*>(po1), v);
        v.x = fmaxf(q02, 0.f); v.y = fmaxf(q03, 0.f);
        v.z = fmaxf(q12, 0.f); v.w = fmaxf(q13, 0.f);
        __stcs(reinterpret_cast<float4*>(po1 + 128), v);
        po0 += tstride;
        po1 += tstride;

        // roll both A windows: t -> t+8  (A_{t+8}[k] = A_t[k+4])
        if (n < NSTEP - 1) {
            float fa0 = pA0[(8 * n + 64) * XS];
            float fa1 = pA0[(8 * n + 64) * XS + 8];
            float fb0 = pA1[(8 * n + 64) * XS];
            float fb1 = pA1[(8 * n + 64) * XS + 8];
#pragma unroll
            for (int s = 0; s < 4; s++) {
                A0a[s] = A2a[s]; A1a[s] = A3a[s];
                A0b[s] = A2b[s]; A1b[s] = A3b[s];
                if (s < 3) {
                    A2a[s] = A0a[s + 1]; A3a[s] = A1a[s + 1];
                    A2b[s] = A0b[s + 1]; A3b[s] = A1b[s + 1];
                }
            }
            A2a[3] = fa0; A3a[3] = fa1;
            A2b[3] = fb0; A3b[3] = fb1;
        }
    }
}

extern "C" void kernel_launch(void* const* d_in, const int* in_sizes, int n_in,
                              void* d_out, int out_size) {
    const float* x    = (const float*)d_in[0];
    const float* w    = (const float*)d_in[1];
    const float* bias = (const float*)d_in[2];
    float* out        = (float*)d_out;

    prep_kernel<<<1, 32>>>(w);

    dim3 grid(NI / CHB, T_DIM / TC);
    conv_kernel<<<grid, 128>>>(x, bias, out);
}